// round 13
// baseline (speedup 1.0000x reference)
#include <cuda_runtime.h>
#include <cuda_bf16.h>
#include <math.h>
#include <stdint.h>

// Problem dims
#define B_  256
#define T_  512
#define D_  256
#define U_  512
#define ZC  2048   // 4*U, gate-interleaved columns: col = 4*u + g, g in {f,i,c,o}

// ---------------- device scratch (static: no allocations allowed) ----------------
__device__ float          g_xw[(size_t)T_ * B_ * ZC];   // 1 GiB: xw[t][b][col] (bias folded in)
__device__ __nv_bfloat16  g_Ur_hi[U_ * ZC];
__device__ __nv_bfloat16  g_Ur_lo[U_ * ZC];
__device__ __nv_bfloat16  g_W_hi[D_ * ZC];
__device__ __nv_bfloat16  g_W_lo[D_ * ZC];
__device__ float          g_bias[ZC];
__device__ float          g_H[2][B_ * U_];              // ping-pong hidden state
__device__ float          g_C[B_ * U_];                 // cell state

// ---------------- PTX helpers ----------------
__device__ __forceinline__ uint32_t smem_u32(const void* p) {
    return (uint32_t)__cvta_generic_to_shared(p);
}

__device__ __forceinline__ void ldsm4(uint32_t& r0, uint32_t& r1, uint32_t& r2, uint32_t& r3,
                                      uint32_t addr) {
    asm volatile("ldmatrix.sync.aligned.m8n8.x4.shared.b16 {%0,%1,%2,%3}, [%4];"
                 : "=r"(r0), "=r"(r1), "=r"(r2), "=r"(r3) : "r"(addr));
}
__device__ __forceinline__ void ldsm2t(uint32_t& r0, uint32_t& r1, uint32_t addr) {
    asm volatile("ldmatrix.sync.aligned.m8n8.x2.trans.shared.b16 {%0,%1}, [%2];"
                 : "=r"(r0), "=r"(r1) : "r"(addr));
}
__device__ __forceinline__ void mma_bf16(float* d, const uint32_t* a, const uint32_t* b) {
    asm volatile(
        "mma.sync.aligned.m16n8k16.row.col.f32.bf16.bf16.f32 "
        "{%0,%1,%2,%3}, {%4,%5,%6,%7}, {%8,%9}, {%0,%1,%2,%3};"
        : "+f"(d[0]), "+f"(d[1]), "+f"(d[2]), "+f"(d[3])
        : "r"(a[0]), "r"(a[1]), "r"(a[2]), "r"(a[3]), "r"(b[0]), "r"(b[1]));
}

// ---------------- prep: permute+fuse weights (col = 4u+g), bf16 hi/lo split, bias fold,
// zero h0/c0 (must re-run every launch for determinism) ----------------
__global__ void prep_kernel(const float* __restrict__ Uf, const float* __restrict__ Ui,
                            const float* __restrict__ Uc, const float* __restrict__ Uo,
                            const float* __restrict__ Wf, const float* __restrict__ Wi,
                            const float* __restrict__ Wc, const float* __restrict__ Wo,
                            const float* __restrict__ bf, const float* __restrict__ bi,
                            const float* __restrict__ bc, const float* __restrict__ bo)
{
    int idx = blockIdx.x * blockDim.x + threadIdx.x;   // 0 .. 1048575

    {   // recurrent weights: [512][2048]
        int k = idx >> 11, col = idx & (ZC - 1);
        int u = col >> 2, g = col & 3;
        const float* Ug = (g == 0) ? Uf : (g == 1) ? Ui : (g == 2) ? Uc : Uo;
        float v = Ug[k * U_ + u];
        __nv_bfloat16 hi = __float2bfloat16(v);
        g_Ur_hi[idx] = hi;
        g_Ur_lo[idx] = __float2bfloat16(v - __bfloat162float(hi));
    }
    if (idx < D_ * ZC) {   // input weights: [256][2048]
        int k = idx >> 11, col = idx & (ZC - 1);
        int u = col >> 2, g = col & 3;
        const float* Wg = (g == 0) ? Wf : (g == 1) ? Wi : (g == 2) ? Wc : Wo;
        float v = Wg[k * U_ + u];
        __nv_bfloat16 hi = __float2bfloat16(v);
        g_W_hi[idx] = hi;
        g_W_lo[idx] = __float2bfloat16(v - __bfloat162float(hi));
    }
    if (idx < ZC) {
        int u = idx >> 2, g = idx & 3;
        g_bias[idx] = ((g == 0) ? bf : (g == 1) ? bi : (g == 2) ? bc : bo)[u];
    }
    if (idx < B_ * U_) {
        g_H[0][idx] = 0.f;
        g_C[idx] = 0.f;
    }
}

// ---------------- phase 1: xw[t][b][col] = x @ Wp + bias, bf16x3 mma ----------------
// CTA tile 64x64, 4 warps (2x2), warp tile 32x32 (2 m-frags x 4 n-frags), BK=16.
__global__ __launch_bounds__(128) void xw_gemm_kernel(const float* __restrict__ x)
{
    __shared__ __nv_bfloat16 As_hi[64][24], As_lo[64][24];   // pad->48B rows: LDSM conflict-free
    __shared__ __nv_bfloat16 Bs_hi[16][72], Bs_lo[16][72];   // pad->144B rows

    const int tid = threadIdx.x;
    const int warp = tid >> 5, lane = tid & 31;
    const int wm = warp >> 1, wn = warp & 1;
    const int rowbase = blockIdx.y * 64;     // row in M = B*T  (row = b*T + t)
    const int colbase = blockIdx.x * 64;

    float acc[2][4][4];
    #pragma unroll
    for (int i = 0; i < 2; i++)
        #pragma unroll
        for (int j = 0; j < 4; j++)
            #pragma unroll
            for (int v = 0; v < 4; v++) acc[i][j][v] = 0.f;

    for (int kk = 0; kk < D_; kk += 16) {
        #pragma unroll
        for (int i = 0; i < 8; i++) {        // A: 64x16 fp32 -> hi/lo bf16
            int e = tid + i * 128;
            int r = e >> 4, k = e & 15;
            float v = x[(size_t)(rowbase + r) * D_ + kk + k];
            __nv_bfloat16 hi = __float2bfloat16(v);
            As_hi[r][k] = hi;
            As_lo[r][k] = __float2bfloat16(v - __bfloat162float(hi));
        }
        #pragma unroll
        for (int i = 0; i < 8; i++) {        // B: 16x64, pre-split
            int e = tid + i * 128;
            int k = e >> 6, n = e & 63;
            size_t gi = (size_t)(kk + k) * ZC + colbase + n;
            Bs_hi[k][n] = g_W_hi[gi];
            Bs_lo[k][n] = g_W_lo[gi];
        }
        __syncthreads();

        uint32_t ah[2][4], al[2][4], bh[4][2], bl[4][2];
        const int arow_in = lane & 15, ahalf = (lane >> 4) * 8;
        #pragma unroll
        for (int mi = 0; mi < 2; mi++) {
            int r = wm * 32 + mi * 16 + arow_in;
            ldsm4(ah[mi][0], ah[mi][1], ah[mi][2], ah[mi][3], smem_u32(&As_hi[r][ahalf]));
            ldsm4(al[mi][0], al[mi][1], al[mi][2], al[mi][3], smem_u32(&As_lo[r][ahalf]));
        }
        const int brow = lane & 15;
        #pragma unroll
        for (int ni = 0; ni < 4; ni++) {
            int bcol = wn * 32 + ni * 8;
            ldsm2t(bh[ni][0], bh[ni][1], smem_u32(&Bs_hi[brow][bcol]));
            ldsm2t(bl[ni][0], bl[ni][1], smem_u32(&Bs_lo[brow][bcol]));
        }
        #pragma unroll
        for (int mi = 0; mi < 2; mi++)
            #pragma unroll
            for (int ni = 0; ni < 4; ni++) {
                mma_bf16(acc[mi][ni], ah[mi], bh[ni]);   // hi*hi
                mma_bf16(acc[mi][ni], ah[mi], bl[ni]);   // hi*lo
                mma_bf16(acc[mi][ni], al[mi], bh[ni]);   // lo*hi
            }
        __syncthreads();
    }

    // epilogue: + bias, scatter to xw[t][b][col]
    const int r0 = lane >> 2, c0 = (lane & 3) * 2;
    #pragma unroll
    for (int mi = 0; mi < 2; mi++)
        #pragma unroll
        for (int ni = 0; ni < 4; ni++) {
            int c = colbase + wn * 32 + ni * 8 + c0;
            int R = rowbase + wm * 32 + mi * 16 + r0;
            float bx = g_bias[c], by = g_bias[c + 1];
            {
                int b = R >> 9, t = R & 511;
                float2 v = make_float2(acc[mi][ni][0] + bx, acc[mi][ni][1] + by);
                *(float2*)&g_xw[((size_t)t * B_ + b) * ZC + c] = v;
            }
            {
                int R2 = R + 8;
                int b = R2 >> 9, t = R2 & 511;
                float2 v = make_float2(acc[mi][ni][2] + bx, acc[mi][ni][3] + by);
                *(float2*)&g_xw[((size_t)t * B_ + b) * ZC + c] = v;
            }
        }
}

// ---------------- phase 2: one timestep. z = xw[t] + h@Ur, fused gate epilogue ----------
// grid (32, 4): 32 col-tiles (16 u each) x 4 row-tiles (64 batch each). 128 CTAs.
__global__ __launch_bounds__(128) void step_kernel(int t,
                                                   const float* __restrict__ Pf,
                                                   const float* __restrict__ Pi,
                                                   const float* __restrict__ Po,
                                                   float* __restrict__ out)
{
    __shared__ __nv_bfloat16 As_hi[64][24], As_lo[64][24];
    __shared__ __nv_bfloat16 Bs_hi[16][72], Bs_lo[16][72];
    __shared__ float zs[64][68];

    const float* __restrict__ Hprev = g_H[t & 1];
    float* __restrict__ Hnext = g_H[(t + 1) & 1];

    const int tid = threadIdx.x;
    const int warp = tid >> 5, lane = tid & 31;
    const int wm = warp >> 1, wn = warp & 1;
    const int rowbase = blockIdx.y * 64;     // batch rows
    const int colbase = blockIdx.x * 64;     // z columns (= 16 u-indices * 4 gates)

    float acc[2][4][4];
    #pragma unroll
    for (int i = 0; i < 2; i++)
        #pragma unroll
        for (int j = 0; j < 4; j++)
            #pragma unroll
            for (int v = 0; v < 4; v++) acc[i][j][v] = 0.f;

    for (int kk = 0; kk < U_; kk += 16) {
        #pragma unroll
        for (int i = 0; i < 8; i++) {        // A: h tile 64x16, split on the fly
            int e = tid + i * 128;
            int r = e >> 4, k = e & 15;
            float v = Hprev[(size_t)(rowbase + r) * U_ + kk + k];
            __nv_bfloat16 hi = __float2bfloat16(v);
            As_hi[r][k] = hi;
            As_lo[r][k] = __float2bfloat16(v - __bfloat162float(hi));
        }
        #pragma unroll
        for (int i = 0; i < 8; i++) {        // B: Ur tile 16x64 (L2-resident, 4 MB)
            int e = tid + i * 128;
            int k = e >> 6, n = e & 63;
            size_t gi = (size_t)(kk + k) * ZC + colbase + n;
            Bs_hi[k][n] = g_Ur_hi[gi];
            Bs_lo[k][n] = g_Ur_lo[gi];
        }
        __syncthreads();

        uint32_t ah[2][4], al[2][4], bh[4][2], bl[4][2];
        const int arow_in = lane & 15, ahalf = (lane >> 4) * 8;
        #pragma unroll
        for (int mi = 0; mi < 2; mi++) {
            int r = wm * 32 + mi * 16 + arow_in;
            ldsm4(ah[mi][0], ah[mi][1], ah[mi][2], ah[mi][3], smem_u32(&As_hi[r][ahalf]));
            ldsm4(al[mi][0], al[mi][1], al[mi][2], al[mi][3], smem_u32(&As_lo[r][ahalf]));
        }
        const int brow = lane & 15;
        #pragma unroll
        for (int ni = 0; ni < 4; ni++) {
            int bcol = wn * 32 + ni * 8;
            ldsm2t(bh[ni][0], bh[ni][1], smem_u32(&Bs_hi[brow][bcol]));
            ldsm2t(bl[ni][0], bl[ni][1], smem_u32(&Bs_lo[brow][bcol]));
        }
        #pragma unroll
        for (int mi = 0; mi < 2; mi++)
            #pragma unroll
            for (int ni = 0; ni < 4; ni++) {
                mma_bf16(acc[mi][ni], ah[mi], bh[ni]);
                mma_bf16(acc[mi][ni], ah[mi], bl[ni]);
                mma_bf16(acc[mi][ni], al[mi], bh[ni]);
            }
        __syncthreads();
    }

    // stage z = acc + xw[t] into smem
    const float* __restrict__ xw_t = g_xw + (size_t)t * B_ * ZC;
    const int r0 = lane >> 2, c0 = (lane & 3) * 2;
    #pragma unroll
    for (int mi = 0; mi < 2; mi++)
        #pragma unroll
        for (int ni = 0; ni < 4; ni++) {
            int r = wm * 32 + mi * 16 + r0;
            int cl = wn * 32 + ni * 8 + c0;
            int Cg = colbase + cl;
            int b = rowbase + r;
            float2 xv0 = *(const float2*)&xw_t[(size_t)b * ZC + Cg];
            zs[r][cl]     = acc[mi][ni][0] + xv0.x;
            zs[r][cl + 1] = acc[mi][ni][1] + xv0.y;
            float2 xv1 = *(const float2*)&xw_t[(size_t)(b + 8) * ZC + Cg];
            zs[r + 8][cl]     = acc[mi][ni][2] + xv1.x;
            zs[r + 8][cl + 1] = acc[mi][ni][3] + xv1.y;
        }
    __syncthreads();

    // fused peephole-LSTM gate epilogue: 64 rows x 16 u per CTA
    #pragma unroll
    for (int e = tid; e < 64 * 16; e += 128) {
        int r = e >> 4, ul = e & 15;
        int b = rowbase + r;
        int u = blockIdx.x * 16 + ul;
        float zf = zs[r][4 * ul + 0];
        float zi = zs[r][4 * ul + 1];
        float zc = zs[r][4 * ul + 2];
        float zo = zs[r][4 * ul + 3];
        int cu = b * U_ + u;
        float cold = g_C[cu];
        float f  = 1.f / (1.f + expf(-(zf + cold * Pf[u])));
        float ig = 1.f / (1.f + expf(-(zi + cold * Pi[u])));
        float cc = tanhf(zc);
        float cn = f * cold + ig * cc;
        float o  = 1.f / (1.f + expf(-(zo + cn * Po[u])));
        float hn = o * tanhf(cn);
        g_C[cu] = cn;
        Hnext[cu] = hn;
        out[((size_t)b * T_ + t) * U_ + u] = hn;
    }
}

// ---------------- launch ----------------
extern "C" void kernel_launch(void* const* d_in, const int* in_sizes, int n_in,
                              void* d_out, int out_size)
{
    (void)in_sizes; (void)n_in; (void)out_size;
    const float* x  = (const float*)d_in[0];
    const float* Wf = (const float*)d_in[1];
    const float* Uf = (const float*)d_in[2];
    const float* Pf = (const float*)d_in[3];
    const float* bf = (const float*)d_in[4];
    const float* Wi = (const float*)d_in[5];
    const float* Ui = (const float*)d_in[6];
    const float* Pi = (const float*)d_in[7];
    const float* bi = (const float*)d_in[8];
    const float* Wc = (const float*)d_in[9];
    const float* Uc = (const float*)d_in[10];
    const float* bc = (const float*)d_in[11];
    const float* Wo = (const float*)d_in[12];
    const float* Uo = (const float*)d_in[13];
    const float* Po = (const float*)d_in[14];
    const float* bo = (const float*)d_in[15];
    float* out = (float*)d_out;

    // 1) pack/split weights, zero state (every call: deterministic graph)
    prep_kernel<<<4096, 256>>>(Uf, Ui, Uc, Uo, Wf, Wi, Wc, Wo, bf, bi, bc, bo);

    // 2) all input projections in one big GEMM: M=131072, N=2048, K=256
    xw_gemm_kernel<<<dim3(32, 2048), 128>>>(x);

    // 3) 512 sequential recurrent steps
    for (int t = 0; t < T_; t++)
        step_kernel<<<dim3(32, 4), 128>>>(t, Pf, Pi, Po, out);
}

// round 14
// speedup vs baseline: 1.0004x; 1.0004x over previous
#include <cuda_runtime.h>
#include <cuda_bf16.h>
#include <math.h>
#include <stdint.h>

// Problem dims
#define B_  256
#define T_  512
#define D_  256
#define U_  512
#define ZC  2048   // 4*U, gate-interleaved columns: col = 4*u + g, g in {f,i,c,o}

// ---------------- device scratch (static: no allocations allowed) ----------------
__device__ float          g_xw[(size_t)T_ * B_ * ZC];   // 1 GiB: xw[t][b][col] (bias folded in)
__device__ __nv_bfloat16  g_Ur_hi[U_ * ZC];
__device__ __nv_bfloat16  g_Ur_lo[U_ * ZC];
__device__ __nv_bfloat16  g_W_hi[D_ * ZC];
__device__ __nv_bfloat16  g_W_lo[D_ * ZC];
__device__ float          g_bias[ZC];
__device__ float          g_H[2][B_ * U_];              // ping-pong hidden state
__device__ float          g_C[B_ * U_];                 // cell state

// ---------------- PTX helpers ----------------
__device__ __forceinline__ uint32_t smem_u32(const void* p) {
    return (uint32_t)__cvta_generic_to_shared(p);
}

__device__ __forceinline__ void ldsm4(uint32_t& r0, uint32_t& r1, uint32_t& r2, uint32_t& r3,
                                      uint32_t addr) {
    asm volatile("ldmatrix.sync.aligned.m8n8.x4.shared.b16 {%0,%1,%2,%3}, [%4];"
                 : "=r"(r0), "=r"(r1), "=r"(r2), "=r"(r3) : "r"(addr));
}
__device__ __forceinline__ void ldsm2t(uint32_t& r0, uint32_t& r1, uint32_t addr) {
    asm volatile("ldmatrix.sync.aligned.m8n8.x2.trans.shared.b16 {%0,%1}, [%2];"
                 : "=r"(r0), "=r"(r1) : "r"(addr));
}
__device__ __forceinline__ void mma_bf16(float* d, const uint32_t* a, const uint32_t* b) {
    asm volatile(
        "mma.sync.aligned.m16n8k16.row.col.f32.bf16.bf16.f32 "
        "{%0,%1,%2,%3}, {%4,%5,%6,%7}, {%8,%9}, {%0,%1,%2,%3};"
        : "+f"(d[0]), "+f"(d[1]), "+f"(d[2]), "+f"(d[3])
        : "r"(a[0]), "r"(a[1]), "r"(a[2]), "r"(a[3]), "r"(b[0]), "r"(b[1]));
}

// ---------------- prep: permute+fuse weights (col = 4u+g), bf16 hi/lo split, bias fold,
// zero h0/c0 (must re-run every launch for determinism) ----------------
__global__ void prep_kernel(const float* __restrict__ Uf, const float* __restrict__ Ui,
                            const float* __restrict__ Uc, const float* __restrict__ Uo,
                            const float* __restrict__ Wf, const float* __restrict__ Wi,
                            const float* __restrict__ Wc, const float* __restrict__ Wo,
                            const float* __restrict__ bf, const float* __restrict__ bi,
                            const float* __restrict__ bc, const float* __restrict__ bo)
{
    int idx = blockIdx.x * blockDim.x + threadIdx.x;   // 0 .. 1048575

    {   // recurrent weights: [512][2048]
        int k = idx >> 11, col = idx & (ZC - 1);
        int u = col >> 2, g = col & 3;
        const float* Ug = (g == 0) ? Uf : (g == 1) ? Ui : (g == 2) ? Uc : Uo;
        float v = Ug[k * U_ + u];
        __nv_bfloat16 hi = __float2bfloat16(v);
        g_Ur_hi[idx] = hi;
        g_Ur_lo[idx] = __float2bfloat16(v - __bfloat162float(hi));
    }
    if (idx < D_ * ZC) {   // input weights: [256][2048]
        int k = idx >> 11, col = idx & (ZC - 1);
        int u = col >> 2, g = col & 3;
        const float* Wg = (g == 0) ? Wf : (g == 1) ? Wi : (g == 2) ? Wc : Wo;
        float v = Wg[k * U_ + u];
        __nv_bfloat16 hi = __float2bfloat16(v);
        g_W_hi[idx] = hi;
        g_W_lo[idx] = __float2bfloat16(v - __bfloat162float(hi));
    }
    if (idx < ZC) {
        int u = idx >> 2, g = idx & 3;
        g_bias[idx] = ((g == 0) ? bf : (g == 1) ? bi : (g == 2) ? bc : bo)[u];
    }
    if (idx < B_ * U_) {
        g_H[0][idx] = 0.f;
        g_C[idx] = 0.f;
    }
}

// ---------------- phase 1: xw[t][b][col] = x @ Wp + bias, bf16x3 mma ----------------
// CTA tile 64x64, 4 warps (2x2), warp tile 32x32 (2 m-frags x 4 n-frags), BK=16.
__global__ __launch_bounds__(128) void xw_gemm_kernel(const float* __restrict__ x)
{
    __shared__ __nv_bfloat16 As_hi[64][24], As_lo[64][24];   // pad->48B rows: LDSM conflict-free
    __shared__ __nv_bfloat16 Bs_hi[16][72], Bs_lo[16][72];   // pad->144B rows

    const int tid = threadIdx.x;
    const int warp = tid >> 5, lane = tid & 31;
    const int wm = warp >> 1, wn = warp & 1;
    const int rowbase = blockIdx.y * 64;     // row in M = B*T  (row = b*T + t)
    const int colbase = blockIdx.x * 64;

    float acc[2][4][4];
    #pragma unroll
    for (int i = 0; i < 2; i++)
        #pragma unroll
        for (int j = 0; j < 4; j++)
            #pragma unroll
            for (int v = 0; v < 4; v++) acc[i][j][v] = 0.f;

    for (int kk = 0; kk < D_; kk += 16) {
        #pragma unroll
        for (int i = 0; i < 8; i++) {        // A: 64x16 fp32 -> hi/lo bf16
            int e = tid + i * 128;
            int r = e >> 4, k = e & 15;
            float v = x[(size_t)(rowbase + r) * D_ + kk + k];
            __nv_bfloat16 hi = __float2bfloat16(v);
            As_hi[r][k] = hi;
            As_lo[r][k] = __float2bfloat16(v - __bfloat162float(hi));
        }
        #pragma unroll
        for (int i = 0; i < 8; i++) {        // B: 16x64, pre-split
            int e = tid + i * 128;
            int k = e >> 6, n = e & 63;
            size_t gi = (size_t)(kk + k) * ZC + colbase + n;
            Bs_hi[k][n] = g_W_hi[gi];
            Bs_lo[k][n] = g_W_lo[gi];
        }
        __syncthreads();

        uint32_t ah[2][4], al[2][4], bh[4][2], bl[4][2];
        const int arow_in = lane & 15, ahalf = (lane >> 4) * 8;
        #pragma unroll
        for (int mi = 0; mi < 2; mi++) {
            int r = wm * 32 + mi * 16 + arow_in;
            ldsm4(ah[mi][0], ah[mi][1], ah[mi][2], ah[mi][3], smem_u32(&As_hi[r][ahalf]));
            ldsm4(al[mi][0], al[mi][1], al[mi][2], al[mi][3], smem_u32(&As_lo[r][ahalf]));
        }
        const int brow = lane & 15;
        #pragma unroll
        for (int ni = 0; ni < 4; ni++) {
            int bcol = wn * 32 + ni * 8;
            ldsm2t(bh[ni][0], bh[ni][1], smem_u32(&Bs_hi[brow][bcol]));
            ldsm2t(bl[ni][0], bl[ni][1], smem_u32(&Bs_lo[brow][bcol]));
        }
        #pragma unroll
        for (int mi = 0; mi < 2; mi++)
            #pragma unroll
            for (int ni = 0; ni < 4; ni++) {
                mma_bf16(acc[mi][ni], ah[mi], bh[ni]);   // hi*hi
                mma_bf16(acc[mi][ni], ah[mi], bl[ni]);   // hi*lo
                mma_bf16(acc[mi][ni], al[mi], bh[ni]);   // lo*hi
            }
        __syncthreads();
    }

    // epilogue: + bias, scatter to xw[t][b][col]
    const int r0 = lane >> 2, c0 = (lane & 3) * 2;
    #pragma unroll
    for (int mi = 0; mi < 2; mi++)
        #pragma unroll
        for (int ni = 0; ni < 4; ni++) {
            int c = colbase + wn * 32 + ni * 8 + c0;
            int R = rowbase + wm * 32 + mi * 16 + r0;
            float bx = g_bias[c], by = g_bias[c + 1];
            {
                int b = R >> 9, t = R & 511;
                float2 v = make_float2(acc[mi][ni][0] + bx, acc[mi][ni][1] + by);
                *(float2*)&g_xw[((size_t)t * B_ + b) * ZC + c] = v;
            }
            {
                int R2 = R + 8;
                int b = R2 >> 9, t = R2 & 511;
                float2 v = make_float2(acc[mi][ni][2] + bx, acc[mi][ni][3] + by);
                *(float2*)&g_xw[((size_t)t * B_ + b) * ZC + c] = v;
            }
        }
}

// ---------------- phase 2: one timestep. z = xw[t] + h@Ur, fused gate epilogue ----------
// grid (32, 4): 32 col-tiles (16 u each) x 4 row-tiles (64 batch each). 128 CTAs.
__global__ __launch_bounds__(128) void step_kernel(int t,
                                                   const float* __restrict__ Pf,
                                                   const float* __restrict__ Pi,
                                                   const float* __restrict__ Po,
                                                   float* __restrict__ out)
{
    __shared__ __nv_bfloat16 As_hi[64][24], As_lo[64][24];
    __shared__ __nv_bfloat16 Bs_hi[16][72], Bs_lo[16][72];
    __shared__ float zs[64][68];

    const float* __restrict__ Hprev = g_H[t & 1];
    float* __restrict__ Hnext = g_H[(t + 1) & 1];

    const int tid = threadIdx.x;
    const int warp = tid >> 5, lane = tid & 31;
    const int wm = warp >> 1, wn = warp & 1;
    const int rowbase = blockIdx.y * 64;     // batch rows
    const int colbase = blockIdx.x * 64;     // z columns (= 16 u-indices * 4 gates)

    float acc[2][4][4];
    #pragma unroll
    for (int i = 0; i < 2; i++)
        #pragma unroll
        for (int j = 0; j < 4; j++)
            #pragma unroll
            for (int v = 0; v < 4; v++) acc[i][j][v] = 0.f;

    for (int kk = 0; kk < U_; kk += 16) {
        #pragma unroll
        for (int i = 0; i < 8; i++) {        // A: h tile 64x16, split on the fly
            int e = tid + i * 128;
            int r = e >> 4, k = e & 15;
            float v = Hprev[(size_t)(rowbase + r) * U_ + kk + k];
            __nv_bfloat16 hi = __float2bfloat16(v);
            As_hi[r][k] = hi;
            As_lo[r][k] = __float2bfloat16(v - __bfloat162float(hi));
        }
        #pragma unroll
        for (int i = 0; i < 8; i++) {        // B: Ur tile 16x64 (L2-resident, 4 MB)
            int e = tid + i * 128;
            int k = e >> 6, n = e & 63;
            size_t gi = (size_t)(kk + k) * ZC + colbase + n;
            Bs_hi[k][n] = g_Ur_hi[gi];
            Bs_lo[k][n] = g_Ur_lo[gi];
        }
        __syncthreads();

        uint32_t ah[2][4], al[2][4], bh[4][2], bl[4][2];
        const int arow_in = lane & 15, ahalf = (lane >> 4) * 8;
        #pragma unroll
        for (int mi = 0; mi < 2; mi++) {
            int r = wm * 32 + mi * 16 + arow_in;
            ldsm4(ah[mi][0], ah[mi][1], ah[mi][2], ah[mi][3], smem_u32(&As_hi[r][ahalf]));
            ldsm4(al[mi][0], al[mi][1], al[mi][2], al[mi][3], smem_u32(&As_lo[r][ahalf]));
        }
        const int brow = lane & 15;
        #pragma unroll
        for (int ni = 0; ni < 4; ni++) {
            int bcol = wn * 32 + ni * 8;
            ldsm2t(bh[ni][0], bh[ni][1], smem_u32(&Bs_hi[brow][bcol]));
            ldsm2t(bl[ni][0], bl[ni][1], smem_u32(&Bs_lo[brow][bcol]));
        }
        #pragma unroll
        for (int mi = 0; mi < 2; mi++)
            #pragma unroll
            for (int ni = 0; ni < 4; ni++) {
                mma_bf16(acc[mi][ni], ah[mi], bh[ni]);
                mma_bf16(acc[mi][ni], ah[mi], bl[ni]);
                mma_bf16(acc[mi][ni], al[mi], bh[ni]);
            }
        __syncthreads();
    }

    // stage z = acc + xw[t] into smem
    const float* __restrict__ xw_t = g_xw + (size_t)t * B_ * ZC;
    const int r0 = lane >> 2, c0 = (lane & 3) * 2;
    #pragma unroll
    for (int mi = 0; mi < 2; mi++)
        #pragma unroll
        for (int ni = 0; ni < 4; ni++) {
            int r = wm * 32 + mi * 16 + r0;
            int cl = wn * 32 + ni * 8 + c0;
            int Cg = colbase + cl;
            int b = rowbase + r;
            float2 xv0 = *(const float2*)&xw_t[(size_t)b * ZC + Cg];
            zs[r][cl]     = acc[mi][ni][0] + xv0.x;
            zs[r][cl + 1] = acc[mi][ni][1] + xv0.y;
            float2 xv1 = *(const float2*)&xw_t[(size_t)(b + 8) * ZC + Cg];
            zs[r + 8][cl]     = acc[mi][ni][2] + xv1.x;
            zs[r + 8][cl + 1] = acc[mi][ni][3] + xv1.y;
        }
    __syncthreads();

    // fused peephole-LSTM gate epilogue: 64 rows x 16 u per CTA
    #pragma unroll
    for (int e = tid; e < 64 * 16; e += 128) {
        int r = e >> 4, ul = e & 15;
        int b = rowbase + r;
        int u = blockIdx.x * 16 + ul;
        float zf = zs[r][4 * ul + 0];
        float zi = zs[r][4 * ul + 1];
        float zc = zs[r][4 * ul + 2];
        float zo = zs[r][4 * ul + 3];
        int cu = b * U_ + u;
        float cold = g_C[cu];
        float f  = 1.f / (1.f + expf(-(zf + cold * Pf[u])));
        float ig = 1.f / (1.f + expf(-(zi + cold * Pi[u])));
        float cc = tanhf(zc);
        float cn = f * cold + ig * cc;
        float o  = 1.f / (1.f + expf(-(zo + cn * Po[u])));
        float hn = o * tanhf(cn);
        g_C[cu] = cn;
        Hnext[cu] = hn;
        out[((size_t)b * T_ + t) * U_ + u] = hn;
    }
}

// ---------------- launch ----------------
extern "C" void kernel_launch(void* const* d_in, const int* in_sizes, int n_in,
                              void* d_out, int out_size)
{
    (void)in_sizes; (void)n_in; (void)out_size;
    const float* x  = (const float*)d_in[0];
    const float* Wf = (const float*)d_in[1];
    const float* Uf = (const float*)d_in[2];
    const float* Pf = (const float*)d_in[3];
    const float* bf = (const float*)d_in[4];
    const float* Wi = (const float*)d_in[5];
    const float* Ui = (const float*)d_in[6];
    const float* Pi = (const float*)d_in[7];
    const float* bi = (const float*)d_in[8];
    const float* Wc = (const float*)d_in[9];
    const float* Uc = (const float*)d_in[10];
    const float* bc = (const float*)d_in[11];
    const float* Wo = (const float*)d_in[12];
    const float* Uo = (const float*)d_in[13];
    const float* Po = (const float*)d_in[14];
    const float* bo = (const float*)d_in[15];
    float* out = (float*)d_out;

    // 1) pack/split weights, zero state (every call: deterministic graph)
    prep_kernel<<<4096, 256>>>(Uf, Ui, Uc, Uo, Wf, Wi, Wc, Wo, bf, bi, bc, bo);

    // 2) all input projections in one big GEMM: M=131072, N=2048, K=256
    xw_gemm_kernel<<<dim3(32, 2048), 128>>>(x);

    // 3) 512 sequential recurrent steps
    for (int t = 0; t < T_; t++)
        step_kernel<<<dim3(32, 4), 128>>>(t, Pf, Pi, Po, out);
}

// round 15
// speedup vs baseline: 1.0022x; 1.0017x over previous
#include <cuda_runtime.h>
#include <cuda_bf16.h>
#include <math.h>
#include <stdint.h>

// Problem dims
#define B_  256
#define T_  512
#define D_  256
#define U_  512
#define ZC  2048   // 4*U, gate-interleaved columns: col = 4*u + g, g in {f,i,c,o}

// ---------------- device scratch (static: no allocations allowed) ----------------
__device__ float          g_xw[(size_t)T_ * B_ * ZC];   // 1 GiB: xw[t][b][col] (bias folded in)
__device__ __nv_bfloat16  g_Ur_hi[U_ * ZC];
__device__ __nv_bfloat16  g_Ur_lo[U_ * ZC];
__device__ __nv_bfloat16  g_W_hi[D_ * ZC];
__device__ __nv_bfloat16  g_W_lo[D_ * ZC];
__device__ float          g_bias[ZC];
__device__ float          g_H[2][B_ * U_];              // ping-pong hidden state
__device__ float          g_C[B_ * U_];                 // cell state

// ---------------- PTX helpers ----------------
__device__ __forceinline__ uint32_t smem_u32(const void* p) {
    return (uint32_t)__cvta_generic_to_shared(p);
}

__device__ __forceinline__ void ldsm4(uint32_t& r0, uint32_t& r1, uint32_t& r2, uint32_t& r3,
                                      uint32_t addr) {
    asm volatile("ldmatrix.sync.aligned.m8n8.x4.shared.b16 {%0,%1,%2,%3}, [%4];"
                 : "=r"(r0), "=r"(r1), "=r"(r2), "=r"(r3) : "r"(addr));
}
__device__ __forceinline__ void ldsm2t(uint32_t& r0, uint32_t& r1, uint32_t addr) {
    asm volatile("ldmatrix.sync.aligned.m8n8.x2.trans.shared.b16 {%0,%1}, [%2];"
                 : "=r"(r0), "=r"(r1) : "r"(addr));
}
__device__ __forceinline__ void mma_bf16(float* d, const uint32_t* a, const uint32_t* b) {
    asm volatile(
        "mma.sync.aligned.m16n8k16.row.col.f32.bf16.bf16.f32 "
        "{%0,%1,%2,%3}, {%4,%5,%6,%7}, {%8,%9}, {%0,%1,%2,%3};"
        : "+f"(d[0]), "+f"(d[1]), "+f"(d[2]), "+f"(d[3])
        : "r"(a[0]), "r"(a[1]), "r"(a[2]), "r"(a[3]), "r"(b[0]), "r"(b[1]));
}

// ---------------- prep: permute+fuse weights (col = 4u+g), bf16 hi/lo split, bias fold,
// zero h0/c0 (must re-run every launch for determinism) ----------------
__global__ void prep_kernel(const float* __restrict__ Uf, const float* __restrict__ Ui,
                            const float* __restrict__ Uc, const float* __restrict__ Uo,
                            const float* __restrict__ Wf, const float* __restrict__ Wi,
                            const float* __restrict__ Wc, const float* __restrict__ Wo,
                            const float* __restrict__ bf, const float* __restrict__ bi,
                            const float* __restrict__ bc, const float* __restrict__ bo)
{
    int idx = blockIdx.x * blockDim.x + threadIdx.x;   // 0 .. 1048575

    {   // recurrent weights: [512][2048]
        int k = idx >> 11, col = idx & (ZC - 1);
        int u = col >> 2, g = col & 3;
        const float* Ug = (g == 0) ? Uf : (g == 1) ? Ui : (g == 2) ? Uc : Uo;
        float v = Ug[k * U_ + u];
        __nv_bfloat16 hi = __float2bfloat16(v);
        g_Ur_hi[idx] = hi;
        g_Ur_lo[idx] = __float2bfloat16(v - __bfloat162float(hi));
    }
    if (idx < D_ * ZC) {   // input weights: [256][2048]
        int k = idx >> 11, col = idx & (ZC - 1);
        int u = col >> 2, g = col & 3;
        const float* Wg = (g == 0) ? Wf : (g == 1) ? Wi : (g == 2) ? Wc : Wo;
        float v = Wg[k * U_ + u];
        __nv_bfloat16 hi = __float2bfloat16(v);
        g_W_hi[idx] = hi;
        g_W_lo[idx] = __float2bfloat16(v - __bfloat162float(hi));
    }
    if (idx < ZC) {
        int u = idx >> 2, g = idx & 3;
        g_bias[idx] = ((g == 0) ? bf : (g == 1) ? bi : (g == 2) ? bc : bo)[u];
    }
    if (idx < B_ * U_) {
        g_H[0][idx] = 0.f;
        g_C[idx] = 0.f;
    }
}

// ---------------- phase 1: xw[t][b][col] = x @ Wp + bias, bf16x3 mma ----------------
// CTA tile 64x64, 4 warps (2x2), warp tile 32x32 (2 m-frags x 4 n-frags), BK=16.
__global__ __launch_bounds__(128) void xw_gemm_kernel(const float* __restrict__ x)
{
    __shared__ __nv_bfloat16 As_hi[64][24], As_lo[64][24];   // pad->48B rows: LDSM conflict-free
    __shared__ __nv_bfloat16 Bs_hi[16][72], Bs_lo[16][72];   // pad->144B rows

    const int tid = threadIdx.x;
    const int warp = tid >> 5, lane = tid & 31;
    const int wm = warp >> 1, wn = warp & 1;
    const int rowbase = blockIdx.y * 64;     // row in M = B*T  (row = b*T + t)
    const int colbase = blockIdx.x * 64;

    float acc[2][4][4];
    #pragma unroll
    for (int i = 0; i < 2; i++)
        #pragma unroll
        for (int j = 0; j < 4; j++)
            #pragma unroll
            for (int v = 0; v < 4; v++) acc[i][j][v] = 0.f;

    for (int kk = 0; kk < D_; kk += 16) {
        #pragma unroll
        for (int i = 0; i < 8; i++) {        // A: 64x16 fp32 -> hi/lo bf16
            int e = tid + i * 128;
            int r = e >> 4, k = e & 15;
            float v = x[(size_t)(rowbase + r) * D_ + kk + k];
            __nv_bfloat16 hi = __float2bfloat16(v);
            As_hi[r][k] = hi;
            As_lo[r][k] = __float2bfloat16(v - __bfloat162float(hi));
        }
        #pragma unroll
        for (int i = 0; i < 8; i++) {        // B: 16x64, pre-split
            int e = tid + i * 128;
            int k = e >> 6, n = e & 63;
            size_t gi = (size_t)(kk + k) * ZC + colbase + n;
            Bs_hi[k][n] = g_W_hi[gi];
            Bs_lo[k][n] = g_W_lo[gi];
        }
        __syncthreads();

        uint32_t ah[2][4], al[2][4], bh[4][2], bl[4][2];
        const int arow_in = lane & 15, ahalf = (lane >> 4) * 8;
        #pragma unroll
        for (int mi = 0; mi < 2; mi++) {
            int r = wm * 32 + mi * 16 + arow_in;
            ldsm4(ah[mi][0], ah[mi][1], ah[mi][2], ah[mi][3], smem_u32(&As_hi[r][ahalf]));
            ldsm4(al[mi][0], al[mi][1], al[mi][2], al[mi][3], smem_u32(&As_lo[r][ahalf]));
        }
        const int brow = lane & 15;
        #pragma unroll
        for (int ni = 0; ni < 4; ni++) {
            int bcol = wn * 32 + ni * 8;
            ldsm2t(bh[ni][0], bh[ni][1], smem_u32(&Bs_hi[brow][bcol]));
            ldsm2t(bl[ni][0], bl[ni][1], smem_u32(&Bs_lo[brow][bcol]));
        }
        #pragma unroll
        for (int mi = 0; mi < 2; mi++)
            #pragma unroll
            for (int ni = 0; ni < 4; ni++) {
                mma_bf16(acc[mi][ni], ah[mi], bh[ni]);   // hi*hi
                mma_bf16(acc[mi][ni], ah[mi], bl[ni]);   // hi*lo
                mma_bf16(acc[mi][ni], al[mi], bh[ni]);   // lo*hi
            }
        __syncthreads();
    }

    // epilogue: + bias, scatter to xw[t][b][col]
    const int r0 = lane >> 2, c0 = (lane & 3) * 2;
    #pragma unroll
    for (int mi = 0; mi < 2; mi++)
        #pragma unroll
        for (int ni = 0; ni < 4; ni++) {
            int c = colbase + wn * 32 + ni * 8 + c0;
            int R = rowbase + wm * 32 + mi * 16 + r0;
            float bx = g_bias[c], by = g_bias[c + 1];
            {
                int b = R >> 9, t = R & 511;
                float2 v = make_float2(acc[mi][ni][0] + bx, acc[mi][ni][1] + by);
                *(float2*)&g_xw[((size_t)t * B_ + b) * ZC + c] = v;
            }
            {
                int R2 = R + 8;
                int b = R2 >> 9, t = R2 & 511;
                float2 v = make_float2(acc[mi][ni][2] + bx, acc[mi][ni][3] + by);
                *(float2*)&g_xw[((size_t)t * B_ + b) * ZC + c] = v;
            }
        }
}

// ---------------- phase 2: one timestep. z = xw[t] + h@Ur, fused gate epilogue ----------
// grid (32, 4): 32 col-tiles (16 u each) x 4 row-tiles (64 batch each). 128 CTAs.
__global__ __launch_bounds__(128) void step_kernel(int t,
                                                   const float* __restrict__ Pf,
                                                   const float* __restrict__ Pi,
                                                   const float* __restrict__ Po,
                                                   float* __restrict__ out)
{
    __shared__ __nv_bfloat16 As_hi[64][24], As_lo[64][24];
    __shared__ __nv_bfloat16 Bs_hi[16][72], Bs_lo[16][72];
    __shared__ float zs[64][68];

    const float* __restrict__ Hprev = g_H[t & 1];
    float* __restrict__ Hnext = g_H[(t + 1) & 1];

    const int tid = threadIdx.x;
    const int warp = tid >> 5, lane = tid & 31;
    const int wm = warp >> 1, wn = warp & 1;
    const int rowbase = blockIdx.y * 64;     // batch rows
    const int colbase = blockIdx.x * 64;     // z columns (= 16 u-indices * 4 gates)

    float acc[2][4][4];
    #pragma unroll
    for (int i = 0; i < 2; i++)
        #pragma unroll
        for (int j = 0; j < 4; j++)
            #pragma unroll
            for (int v = 0; v < 4; v++) acc[i][j][v] = 0.f;

    for (int kk = 0; kk < U_; kk += 16) {
        #pragma unroll
        for (int i = 0; i < 8; i++) {        // A: h tile 64x16, split on the fly
            int e = tid + i * 128;
            int r = e >> 4, k = e & 15;
            float v = Hprev[(size_t)(rowbase + r) * U_ + kk + k];
            __nv_bfloat16 hi = __float2bfloat16(v);
            As_hi[r][k] = hi;
            As_lo[r][k] = __float2bfloat16(v - __bfloat162float(hi));
        }
        #pragma unroll
        for (int i = 0; i < 8; i++) {        // B: Ur tile 16x64 (L2-resident, 4 MB)
            int e = tid + i * 128;
            int k = e >> 6, n = e & 63;
            size_t gi = (size_t)(kk + k) * ZC + colbase + n;
            Bs_hi[k][n] = g_Ur_hi[gi];
            Bs_lo[k][n] = g_Ur_lo[gi];
        }
        __syncthreads();

        uint32_t ah[2][4], al[2][4], bh[4][2], bl[4][2];
        const int arow_in = lane & 15, ahalf = (lane >> 4) * 8;
        #pragma unroll
        for (int mi = 0; mi < 2; mi++) {
            int r = wm * 32 + mi * 16 + arow_in;
            ldsm4(ah[mi][0], ah[mi][1], ah[mi][2], ah[mi][3], smem_u32(&As_hi[r][ahalf]));
            ldsm4(al[mi][0], al[mi][1], al[mi][2], al[mi][3], smem_u32(&As_lo[r][ahalf]));
        }
        const int brow = lane & 15;
        #pragma unroll
        for (int ni = 0; ni < 4; ni++) {
            int bcol = wn * 32 + ni * 8;
            ldsm2t(bh[ni][0], bh[ni][1], smem_u32(&Bs_hi[brow][bcol]));
            ldsm2t(bl[ni][0], bl[ni][1], smem_u32(&Bs_lo[brow][bcol]));
        }
        #pragma unroll
        for (int mi = 0; mi < 2; mi++)
            #pragma unroll
            for (int ni = 0; ni < 4; ni++) {
                mma_bf16(acc[mi][ni], ah[mi], bh[ni]);
                mma_bf16(acc[mi][ni], ah[mi], bl[ni]);
                mma_bf16(acc[mi][ni], al[mi], bh[ni]);
            }
        __syncthreads();
    }

    // stage z = acc + xw[t] into smem
    const float* __restrict__ xw_t = g_xw + (size_t)t * B_ * ZC;
    const int r0 = lane >> 2, c0 = (lane & 3) * 2;
    #pragma unroll
    for (int mi = 0; mi < 2; mi++)
        #pragma unroll
        for (int ni = 0; ni < 4; ni++) {
            int r = wm * 32 + mi * 16 + r0;
            int cl = wn * 32 + ni * 8 + c0;
            int Cg = colbase + cl;
            int b = rowbase + r;
            float2 xv0 = *(const float2*)&xw_t[(size_t)b * ZC + Cg];
            zs[r][cl]     = acc[mi][ni][0] + xv0.x;
            zs[r][cl + 1] = acc[mi][ni][1] + xv0.y;
            float2 xv1 = *(const float2*)&xw_t[(size_t)(b + 8) * ZC + Cg];
            zs[r + 8][cl]     = acc[mi][ni][2] + xv1.x;
            zs[r + 8][cl + 1] = acc[mi][ni][3] + xv1.y;
        }
    __syncthreads();

    // fused peephole-LSTM gate epilogue: 64 rows x 16 u per CTA
    #pragma unroll
    for (int e = tid; e < 64 * 16; e += 128) {
        int r = e >> 4, ul = e & 15;
        int b = rowbase + r;
        int u = blockIdx.x * 16 + ul;
        float zf = zs[r][4 * ul + 0];
        float zi = zs[r][4 * ul + 1];
        float zc = zs[r][4 * ul + 2];
        float zo = zs[r][4 * ul + 3];
        int cu = b * U_ + u;
        float cold = g_C[cu];
        float f  = 1.f / (1.f + expf(-(zf + cold * Pf[u])));
        float ig = 1.f / (1.f + expf(-(zi + cold * Pi[u])));
        float cc = tanhf(zc);
        float cn = f * cold + ig * cc;
        float o  = 1.f / (1.f + expf(-(zo + cn * Po[u])));
        float hn = o * tanhf(cn);
        g_C[cu] = cn;
        Hnext[cu] = hn;
        out[((size_t)b * T_ + t) * U_ + u] = hn;
    }
}

// ---------------- launch ----------------
extern "C" void kernel_launch(void* const* d_in, const int* in_sizes, int n_in,
                              void* d_out, int out_size)
{
    (void)in_sizes; (void)n_in; (void)out_size;
    const float* x  = (const float*)d_in[0];
    const float* Wf = (const float*)d_in[1];
    const float* Uf = (const float*)d_in[2];
    const float* Pf = (const float*)d_in[3];
    const float* bf = (const float*)d_in[4];
    const float* Wi = (const float*)d_in[5];
    const float* Ui = (const float*)d_in[6];
    const float* Pi = (const float*)d_in[7];
    const float* bi = (const float*)d_in[8];
    const float* Wc = (const float*)d_in[9];
    const float* Uc = (const float*)d_in[10];
    const float* bc = (const float*)d_in[11];
    const float* Wo = (const float*)d_in[12];
    const float* Uo = (const float*)d_in[13];
    const float* Po = (const float*)d_in[14];
    const float* bo = (const float*)d_in[15];
    float* out = (float*)d_out;

    // 1) pack/split weights, zero state (every call: deterministic graph)
    prep_kernel<<<4096, 256>>>(Uf, Ui, Uc, Uo, Wf, Wi, Wc, Wo, bf, bi, bc, bo);

    // 2) all input projections in one big GEMM: M=131072, N=2048, K=256
    xw_gemm_kernel<<<dim3(32, 2048), 128>>>(x);

    // 3) 512 sequential recurrent steps
    for (int t = 0; t < T_; t++)
        step_kernel<<<dim3(32, 4), 128>>>(t, Pf, Pi, Po, out);
}

// round 16
// speedup vs baseline: 2.6266x; 2.6210x over previous
#include <cuda_runtime.h>
#include <cuda_bf16.h>
#include <math.h>
#include <stdint.h>

// Problem dims
#define B_  256
#define T_  512
#define D_  256
#define U_  512
#define ZC  2048   // 4*U, gate-interleaved columns: col = 4*u + g, g in {f,i,c,o}

// ---------------- device scratch (static: no allocations allowed) ----------------
__device__ float          g_xw[(size_t)T_ * B_ * ZC];   // 1 GiB: xw[t][b][col] (bias folded)
__device__ __nv_bfloat16  g_Ur_hi[U_ * ZC];
__device__ __nv_bfloat16  g_Ur_lo[U_ * ZC];
__device__ __nv_bfloat16  g_W_hi[D_ * ZC];
__device__ __nv_bfloat16  g_W_lo[D_ * ZC];
__device__ float          g_bias[ZC];
__device__ __nv_bfloat16  g_Hhi[2][B_ * U_];            // ping-pong hidden state, hi part
__device__ __nv_bfloat16  g_Hlo[2][B_ * U_];            // lo part
__device__ unsigned       g_barrier;

// ---------------- PTX helpers ----------------
__device__ __forceinline__ uint32_t smem_u32(const void* p) {
    return (uint32_t)__cvta_generic_to_shared(p);
}
__device__ __forceinline__ void ldsm4(uint32_t& r0, uint32_t& r1, uint32_t& r2, uint32_t& r3,
                                      uint32_t addr) {
    asm volatile("ldmatrix.sync.aligned.m8n8.x4.shared.b16 {%0,%1,%2,%3}, [%4];"
                 : "=r"(r0), "=r"(r1), "=r"(r2), "=r"(r3) : "r"(addr));
}
__device__ __forceinline__ void ldsm2t(uint32_t& r0, uint32_t& r1, uint32_t addr) {
    asm volatile("ldmatrix.sync.aligned.m8n8.x2.trans.shared.b16 {%0,%1}, [%2];"
                 : "=r"(r0), "=r"(r1) : "r"(addr));
}
__device__ __forceinline__ void mma_bf16(float* d, const uint32_t* a, const uint32_t* b) {
    asm volatile(
        "mma.sync.aligned.m16n8k16.row.col.f32.bf16.bf16.f32 "
        "{%0,%1,%2,%3}, {%4,%5,%6,%7}, {%8,%9}, {%0,%1,%2,%3};"
        : "+f"(d[0]), "+f"(d[1]), "+f"(d[2]), "+f"(d[3])
        : "r"(a[0]), "r"(a[1]), "r"(a[2]), "r"(a[3]), "r"(b[0]), "r"(b[1]));
}

__device__ __forceinline__ float sigm(float x) {
    return __fdividef(1.f, 1.f + __expf(-x));
}
__device__ __forceinline__ float tanh_(float x) {
    return __fdividef(2.f, 1.f + __expf(-2.f * x)) - 1.f;
}

// ---------------- prep: permute+fuse weights (col = 4u+g), bf16 hi/lo split, bias fold,
// zero h0 and grid barrier (re-run every launch: deterministic graph) ----------------
__global__ void prep_kernel(const float* __restrict__ Uf, const float* __restrict__ Ui,
                            const float* __restrict__ Uc, const float* __restrict__ Uo,
                            const float* __restrict__ Wf, const float* __restrict__ Wi,
                            const float* __restrict__ Wc, const float* __restrict__ Wo,
                            const float* __restrict__ bf, const float* __restrict__ bi,
                            const float* __restrict__ bc, const float* __restrict__ bo)
{
    int idx = blockIdx.x * blockDim.x + threadIdx.x;   // 0 .. 1048575

    {   // recurrent weights: [512][2048]
        int k = idx >> 11, col = idx & (ZC - 1);
        int u = col >> 2, g = col & 3;
        const float* Ug = (g == 0) ? Uf : (g == 1) ? Ui : (g == 2) ? Uc : Uo;
        float v = Ug[k * U_ + u];
        __nv_bfloat16 hi = __float2bfloat16(v);
        g_Ur_hi[idx] = hi;
        g_Ur_lo[idx] = __float2bfloat16(v - __bfloat162float(hi));
    }
    if (idx < D_ * ZC) {   // input weights: [256][2048]
        int k = idx >> 11, col = idx & (ZC - 1);
        int u = col >> 2, g = col & 3;
        const float* Wg = (g == 0) ? Wf : (g == 1) ? Wi : (g == 2) ? Wc : Wo;
        float v = Wg[k * U_ + u];
        __nv_bfloat16 hi = __float2bfloat16(v);
        g_W_hi[idx] = hi;
        g_W_lo[idx] = __float2bfloat16(v - __bfloat162float(hi));
    }
    if (idx < ZC) {
        int u = idx >> 2, g = idx & 3;
        g_bias[idx] = ((g == 0) ? bf : (g == 1) ? bi : (g == 2) ? bc : bo)[u];
    }
    if (idx < B_ * U_) {
        g_Hhi[0][idx] = __float2bfloat16(0.f);
        g_Hlo[0][idx] = __float2bfloat16(0.f);
    }
    if (idx == 0) g_barrier = 0u;
}

// ---------------- phase 1: xw[t][b][col] = x @ Wp + bias, bf16x3 mma ----------------
__global__ __launch_bounds__(128) void xw_gemm_kernel(const float* __restrict__ x)
{
    __shared__ __nv_bfloat16 As_hi[64][24], As_lo[64][24];
    __shared__ __nv_bfloat16 Bs_hi[16][72], Bs_lo[16][72];

    const int tid = threadIdx.x;
    const int warp = tid >> 5, lane = tid & 31;
    const int wm = warp >> 1, wn = warp & 1;
    const int rowbase = blockIdx.y * 64;     // row in M = B*T (row = b*T + t)
    const int colbase = blockIdx.x * 64;

    float acc[2][4][4];
    #pragma unroll
    for (int i = 0; i < 2; i++)
        #pragma unroll
        for (int j = 0; j < 4; j++)
            #pragma unroll
            for (int v = 0; v < 4; v++) acc[i][j][v] = 0.f;

    for (int kk = 0; kk < D_; kk += 16) {
        #pragma unroll
        for (int i = 0; i < 8; i++) {
            int e = tid + i * 128;
            int r = e >> 4, k = e & 15;
            float v = x[(size_t)(rowbase + r) * D_ + kk + k];
            __nv_bfloat16 hi = __float2bfloat16(v);
            As_hi[r][k] = hi;
            As_lo[r][k] = __float2bfloat16(v - __bfloat162float(hi));
        }
        #pragma unroll
        for (int i = 0; i < 8; i++) {
            int e = tid + i * 128;
            int k = e >> 6, n = e & 63;
            size_t gi = (size_t)(kk + k) * ZC + colbase + n;
            Bs_hi[k][n] = g_W_hi[gi];
            Bs_lo[k][n] = g_W_lo[gi];
        }
        __syncthreads();

        uint32_t ah[2][4], al[2][4], bh[4][2], bl[4][2];
        const int arow_in = lane & 15, ahalf = (lane >> 4) * 8;
        #pragma unroll
        for (int mi = 0; mi < 2; mi++) {
            int r = wm * 32 + mi * 16 + arow_in;
            ldsm4(ah[mi][0], ah[mi][1], ah[mi][2], ah[mi][3], smem_u32(&As_hi[r][ahalf]));
            ldsm4(al[mi][0], al[mi][1], al[mi][2], al[mi][3], smem_u32(&As_lo[r][ahalf]));
        }
        const int brow = lane & 15;
        #pragma unroll
        for (int ni = 0; ni < 4; ni++) {
            int bcol = wn * 32 + ni * 8;
            ldsm2t(bh[ni][0], bh[ni][1], smem_u32(&Bs_hi[brow][bcol]));
            ldsm2t(bl[ni][0], bl[ni][1], smem_u32(&Bs_lo[brow][bcol]));
        }
        #pragma unroll
        for (int mi = 0; mi < 2; mi++)
            #pragma unroll
            for (int ni = 0; ni < 4; ni++) {
                mma_bf16(acc[mi][ni], ah[mi], bh[ni]);
                mma_bf16(acc[mi][ni], ah[mi], bl[ni]);
                mma_bf16(acc[mi][ni], al[mi], bh[ni]);
            }
        __syncthreads();
    }

    const int r0 = lane >> 2, c0 = (lane & 3) * 2;
    #pragma unroll
    for (int mi = 0; mi < 2; mi++)
        #pragma unroll
        for (int ni = 0; ni < 4; ni++) {
            int c = colbase + wn * 32 + ni * 8 + c0;
            int R = rowbase + wm * 32 + mi * 16 + r0;
            float bx = g_bias[c], by = g_bias[c + 1];
            {
                int b = R >> 9, t = R & 511;
                float2 v = make_float2(acc[mi][ni][0] + bx, acc[mi][ni][1] + by);
                *(float2*)&g_xw[((size_t)t * B_ + b) * ZC + c] = v;
            }
            {
                int R2 = R + 8;
                int b = R2 >> 9, t = R2 & 511;
                float2 v = make_float2(acc[mi][ni][2] + bx, acc[mi][ni][3] + by);
                *(float2*)&g_xw[((size_t)t * B_ + b) * ZC + c] = v;
            }
        }
}

// ---------------- phase 2: persistent recurrence kernel ----------------
// 128 CTAs (32 col-tiles x 4 row-tiles), 128 threads each, 1 CTA/SM.
// Per CTA: its 512x64 Ur slice lives in smem for all 512 steps (XOR-swizzled),
// c and peephole vectors live in smem, h ping-pongs through global as bf16 hi/lo.

// smem layout sizes (bytes)
#define SM_BHI   0
#define SM_BLO   (512*64*2)                        //  65536
#define SM_AHI   (SM_BLO + 512*64*2)               // 131072
#define SM_ALO   (SM_AHI + 2*64*64*2)              // 147456
#define SM_ZS    (SM_ALO + 2*64*64*2)              // 163840
#define SM_CS    (SM_ZS + 64*68*4)                 // 181248
#define SM_PS    (SM_CS + 1024*4)                  // 185344
#define SM_TOTAL (SM_PS + 48*4)                    // 185536

__device__ __forceinline__ void grid_barrier(unsigned target) {
    __syncthreads();
    if (threadIdx.x == 0) {
        __threadfence();                           // release H writes
        atomicAdd(&g_barrier, 1u);
        unsigned v;
        do {
            asm volatile("ld.acquire.gpu.global.u32 %0, [%1];"
                         : "=r"(v) : "l"(&g_barrier) : "memory");
        } while (v < target);
    }
    __syncthreads();
}

__global__ __launch_bounds__(128, 1) void lstm_persistent(const float* __restrict__ Pf,
                                                          const float* __restrict__ Pi,
                                                          const float* __restrict__ Po,
                                                          float* __restrict__ out)
{
    extern __shared__ char sm[];
    __nv_bfloat16* Bhi = (__nv_bfloat16*)(sm + SM_BHI);   // [512][64] swizzled
    __nv_bfloat16* Blo = (__nv_bfloat16*)(sm + SM_BLO);
    __nv_bfloat16* Ahi = (__nv_bfloat16*)(sm + SM_AHI);   // [2][64][64] swizzled
    __nv_bfloat16* Alo = (__nv_bfloat16*)(sm + SM_ALO);
    float*         zs  = (float*)(sm + SM_ZS);            // [64][68]
    float*         Cs  = (float*)(sm + SM_CS);            // [64*16]
    float*         Ps  = (float*)(sm + SM_PS);            // [3][16]

    const int tid  = threadIdx.x;
    const int warp = tid >> 5, lane = tid & 31;
    const int wm = warp >> 1, wn = warp & 1;
    const int colCTA = blockIdx.x & 31, rowCTA = blockIdx.x >> 5;
    const int colbase = colCTA * 64;
    const int rowbase = rowCTA * 64;

    // ---- one-time: load persistent Ur slice, zero c, load peepholes ----
    for (int idx = tid; idx < 512 * 8; idx += 128) {       // 8 chunks of 8 bf16 per row
        int k = idx >> 3, c8 = idx & 7;
        size_t gi = (size_t)k * ZC + colbase + c8 * 8;
        int dst = k * 64 + ((c8 ^ (k & 7)) << 3);
        *(uint4*)&Bhi[dst] = *(const uint4*)&g_Ur_hi[gi];
        *(uint4*)&Blo[dst] = *(const uint4*)&g_Ur_lo[gi];
    }
    for (int e = tid; e < 1024; e += 128) Cs[e] = 0.f;
    if (tid < 16) {
        int u = colCTA * 16 + tid;
        Ps[tid]      = Pf[u];
        Ps[16 + tid] = Pi[u];
        Ps[32 + tid] = Po[u];
    }
    __syncthreads();

    const int r0 = lane >> 2, c0 = (lane & 3) * 2;

    #pragma unroll 1
    for (int t = 0; t < T_; t++) {
        const __nv_bfloat16* __restrict__ Hh = g_Hhi[t & 1];
        const __nv_bfloat16* __restrict__ Hl = g_Hlo[t & 1];

        // prefetch this step's xw tile into registers (hides under MMA loop)
        float2 xv[2][4][2];
        {
            const float* __restrict__ xw_t = g_xw + (size_t)t * (B_ * ZC);
            #pragma unroll
            for (int mi = 0; mi < 2; mi++)
                #pragma unroll
                for (int ni = 0; ni < 4; ni++) {
                    int cg = colbase + wn * 32 + ni * 8 + c0;
                    int bg = rowbase + wm * 32 + mi * 16 + r0;
                    xv[mi][ni][0] = *(const float2*)&xw_t[(size_t)bg * ZC + cg];
                    xv[mi][ni][1] = *(const float2*)&xw_t[(size_t)(bg + 8) * ZC + cg];
                }
        }

        // prologue: stage A chunk 0 (k = 0..63)
        #pragma unroll
        for (int i = 0; i < 4; i++) {
            int seg = tid + i * 128;
            int r = seg >> 3, c8 = seg & 7;
            size_t gi = (size_t)(rowbase + r) * U_ + c8 * 8;
            int dst = r * 64 + ((c8 ^ (r & 7)) << 3);
            *(uint4*)&Ahi[dst] = *(const uint4*)&Hh[gi];
            *(uint4*)&Alo[dst] = *(const uint4*)&Hl[gi];
        }
        __syncthreads();

        float acc[2][4][4];
        #pragma unroll
        for (int i = 0; i < 2; i++)
            #pragma unroll
            for (int j = 0; j < 4; j++)
                #pragma unroll
                for (int v = 0; v < 4; v++) acc[i][j][v] = 0.f;

        #pragma unroll
        for (int kc = 0; kc < 8; kc++) {
            const int cur = kc & 1;
            // issue LDGs for next chunk before MMA work
            uint4 ph[4], pl[4];
            if (kc < 7) {
                #pragma unroll
                for (int i = 0; i < 4; i++) {
                    int seg = tid + i * 128;
                    int r = seg >> 3, c8 = seg & 7;
                    size_t gi = (size_t)(rowbase + r) * U_ + (kc + 1) * 64 + c8 * 8;
                    ph[i] = *(const uint4*)&Hh[gi];
                    pl[i] = *(const uint4*)&Hl[gi];
                }
            }
            // 4 x k16 MMA sub-iters over chunk kc
            #pragma unroll
            for (int kt2 = 0; kt2 < 4; kt2++) {
                uint32_t ah[2][4], al[2][4], bh[4][2], bl[4][2];
                const int khalf = kt2 * 2 + (lane >> 4);      // 8-elem chunk within 64
                #pragma unroll
                for (int mi = 0; mi < 2; mi++) {
                    int r = wm * 32 + mi * 16 + (lane & 15);
                    int off = cur * 4096 + r * 64 + ((khalf ^ (r & 7)) << 3);
                    ldsm4(ah[mi][0], ah[mi][1], ah[mi][2], ah[mi][3], smem_u32(&Ahi[off]));
                    ldsm4(al[mi][0], al[mi][1], al[mi][2], al[mi][3], smem_u32(&Alo[off]));
                }
                const int krow = kc * 64 + kt2 * 16 + (lane & 15);
                #pragma unroll
                for (int ni = 0; ni < 4; ni++) {
                    int bc8 = (wn * 4 + ni) ^ (krow & 7);
                    int off = krow * 64 + (bc8 << 3);
                    ldsm2t(bh[ni][0], bh[ni][1], smem_u32(&Bhi[off]));
                    ldsm2t(bl[ni][0], bl[ni][1], smem_u32(&Blo[off]));
                }
                // 3 passes -> 8-MMA RAW distance per accumulator
                #pragma unroll
                for (int mi = 0; mi < 2; mi++)
                    #pragma unroll
                    for (int ni = 0; ni < 4; ni++)
                        mma_bf16(acc[mi][ni], ah[mi], bh[ni]);
                #pragma unroll
                for (int mi = 0; mi < 2; mi++)
                    #pragma unroll
                    for (int ni = 0; ni < 4; ni++)
                        mma_bf16(acc[mi][ni], ah[mi], bl[ni]);
                #pragma unroll
                for (int mi = 0; mi < 2; mi++)
                    #pragma unroll
                    for (int ni = 0; ni < 4; ni++)
                        mma_bf16(acc[mi][ni], al[mi], bh[ni]);
            }
            // store prefetched chunk into other buffer
            if (kc < 7) {
                #pragma unroll
                for (int i = 0; i < 4; i++) {
                    int seg = tid + i * 128;
                    int r = seg >> 3, c8 = seg & 7;
                    int dst = (cur ^ 1) * 4096 + r * 64 + ((c8 ^ (r & 7)) << 3);
                    *(uint4*)&Ahi[dst] = ph[i];
                    *(uint4*)&Alo[dst] = pl[i];
                }
            }
            __syncthreads();
        }

        // stage z = acc + xw into smem
        #pragma unroll
        for (int mi = 0; mi < 2; mi++)
            #pragma unroll
            for (int ni = 0; ni < 4; ni++) {
                int r = wm * 32 + mi * 16 + r0;
                int cl = wn * 32 + ni * 8 + c0;
                zs[r * 68 + cl]           = acc[mi][ni][0] + xv[mi][ni][0].x;
                zs[r * 68 + cl + 1]       = acc[mi][ni][1] + xv[mi][ni][0].y;
                zs[(r + 8) * 68 + cl]     = acc[mi][ni][2] + xv[mi][ni][1].x;
                zs[(r + 8) * 68 + cl + 1] = acc[mi][ni][3] + xv[mi][ni][1].y;
            }
        __syncthreads();

        // fused peephole-LSTM gate epilogue: c stays in smem, h -> global bf16 hi/lo
        __nv_bfloat16* __restrict__ Hh_n = g_Hhi[(t + 1) & 1];
        __nv_bfloat16* __restrict__ Hl_n = g_Hlo[(t + 1) & 1];
        #pragma unroll
        for (int e = tid; e < 1024; e += 128) {
            int r = e >> 4, ul = e & 15;
            int b = rowbase + r;
            int u = colCTA * 16 + ul;
            float zf = zs[r * 68 + 4 * ul + 0];
            float zi = zs[r * 68 + 4 * ul + 1];
            float zc = zs[r * 68 + 4 * ul + 2];
            float zo = zs[r * 68 + 4 * ul + 3];
            float cold = Cs[e];
            float f  = sigm(zf + cold * Ps[ul]);
            float ig = sigm(zi + cold * Ps[16 + ul]);
            float cc = tanh_(zc);
            float cn = f * cold + ig * cc;
            float o  = sigm(zo + cn * Ps[32 + ul]);
            float hn = o * tanh_(cn);
            Cs[e] = cn;
            __nv_bfloat16 hi = __float2bfloat16(hn);
            int gi = b * U_ + u;
            Hh_n[gi] = hi;
            Hl_n[gi] = __float2bfloat16(hn - __bfloat162float(hi));
            out[((size_t)b * T_ + t) * U_ + u] = hn;
        }

        // grid-wide release/acquire barrier before next step reads Hnext
        if (t < T_ - 1) grid_barrier((unsigned)(t + 1) * 128u);
    }
}

// ---------------- launch ----------------
extern "C" void kernel_launch(void* const* d_in, const int* in_sizes, int n_in,
                              void* d_out, int out_size)
{
    (void)in_sizes; (void)n_in; (void)out_size;
    const float* x  = (const float*)d_in[0];
    const float* Wf = (const float*)d_in[1];
    const float* Uf = (const float*)d_in[2];
    const float* Pf = (const float*)d_in[3];
    const float* bf = (const float*)d_in[4];
    const float* Wi = (const float*)d_in[5];
    const float* Ui = (const float*)d_in[6];
    const float* Pi = (const float*)d_in[7];
    const float* bi = (const float*)d_in[8];
    const float* Wc = (const float*)d_in[9];
    const float* Uc = (const float*)d_in[10];
    const float* bc = (const float*)d_in[11];
    const float* Wo = (const float*)d_in[12];
    const float* Uo = (const float*)d_in[13];
    const float* Po = (const float*)d_in[14];
    const float* bo = (const float*)d_in[15];
    float* out = (float*)d_out;

    static bool attr_done = false;
    if (!attr_done) {
        cudaFuncSetAttribute(lstm_persistent,
                             cudaFuncAttributeMaxDynamicSharedMemorySize, SM_TOTAL);
        attr_done = true;
    }

    // 1) pack/split weights, zero state + barrier (every call: deterministic graph)
    prep_kernel<<<4096, 256>>>(Uf, Ui, Uc, Uo, Wf, Wi, Wc, Wo, bf, bi, bc, bo);

    // 2) all input projections in one big GEMM: M=131072, N=2048, K=256
    xw_gemm_kernel<<<dim3(32, 2048), 128>>>(x);

    // 3) persistent recurrence: 128 CTAs, 512 steps, grid barriers between steps
    lstm_persistent<<<128, 128, SM_TOTAL>>>(Pf, Pi, Po, out);
}

// round 17
// speedup vs baseline: 2.6326x; 1.0023x over previous
#include <cuda_runtime.h>
#include <cuda_bf16.h>
#include <math.h>
#include <stdint.h>

// Problem dims
#define B_  256
#define T_  512
#define D_  256
#define U_  512
#define ZC  2048   // 4*U, gate-interleaved columns: col = 4*u + g, g in {f,i,c,o}

// ---------------- device scratch (static: no allocations allowed) ----------------
__device__ float          g_xw[(size_t)T_ * B_ * ZC];   // 1 GiB: xw[t][b][col] (bias folded)
__device__ __nv_bfloat16  g_Ur_hi[U_ * ZC];
__device__ __nv_bfloat16  g_Ur_lo[U_ * ZC];
__device__ __nv_bfloat16  g_W_hi[D_ * ZC];
__device__ __nv_bfloat16  g_W_lo[D_ * ZC];
__device__ float          g_bias[ZC];
__device__ __nv_bfloat16  g_Hhi[2][B_ * U_];            // ping-pong hidden state, hi part
__device__ __nv_bfloat16  g_Hlo[2][B_ * U_];            // lo part
__device__ unsigned       g_barrier;

// ---------------- PTX helpers ----------------
__device__ __forceinline__ uint32_t smem_u32(const void* p) {
    return (uint32_t)__cvta_generic_to_shared(p);
}
__device__ __forceinline__ void ldsm4(uint32_t& r0, uint32_t& r1, uint32_t& r2, uint32_t& r3,
                                      uint32_t addr) {
    asm volatile("ldmatrix.sync.aligned.m8n8.x4.shared.b16 {%0,%1,%2,%3}, [%4];"
                 : "=r"(r0), "=r"(r1), "=r"(r2), "=r"(r3) : "r"(addr));
}
__device__ __forceinline__ void ldsm2t(uint32_t& r0, uint32_t& r1, uint32_t addr) {
    asm volatile("ldmatrix.sync.aligned.m8n8.x2.trans.shared.b16 {%0,%1}, [%2];"
                 : "=r"(r0), "=r"(r1) : "r"(addr));
}
__device__ __forceinline__ void mma_bf16(float* d, const uint32_t* a, const uint32_t* b) {
    asm volatile(
        "mma.sync.aligned.m16n8k16.row.col.f32.bf16.bf16.f32 "
        "{%0,%1,%2,%3}, {%4,%5,%6,%7}, {%8,%9}, {%0,%1,%2,%3};"
        : "+f"(d[0]), "+f"(d[1]), "+f"(d[2]), "+f"(d[3])
        : "r"(a[0]), "r"(a[1]), "r"(a[2]), "r"(a[3]), "r"(b[0]), "r"(b[1]));
}

__device__ __forceinline__ float sigm(float x) {
    return __fdividef(1.f, 1.f + __expf(-x));
}
__device__ __forceinline__ float tanh_(float x) {
    return __fdividef(2.f, 1.f + __expf(-2.f * x)) - 1.f;
}

// ---------------- prep: permute+fuse weights (col = 4u+g), bf16 hi/lo split, bias fold,
// zero h0 and grid barrier (re-run every launch: deterministic graph) ----------------
__global__ void prep_kernel(const float* __restrict__ Uf, const float* __restrict__ Ui,
                            const float* __restrict__ Uc, const float* __restrict__ Uo,
                            const float* __restrict__ Wf, const float* __restrict__ Wi,
                            const float* __restrict__ Wc, const float* __restrict__ Wo,
                            const float* __restrict__ bf, const float* __restrict__ bi,
                            const float* __restrict__ bc, const float* __restrict__ bo)
{
    int idx = blockIdx.x * blockDim.x + threadIdx.x;   // 0 .. 1048575

    {   // recurrent weights: [512][2048]
        int k = idx >> 11, col = idx & (ZC - 1);
        int u = col >> 2, g = col & 3;
        const float* Ug = (g == 0) ? Uf : (g == 1) ? Ui : (g == 2) ? Uc : Uo;
        float v = Ug[k * U_ + u];
        __nv_bfloat16 hi = __float2bfloat16(v);
        g_Ur_hi[idx] = hi;
        g_Ur_lo[idx] = __float2bfloat16(v - __bfloat162float(hi));
    }
    if (idx < D_ * ZC) {   // input weights: [256][2048]
        int k = idx >> 11, col = idx & (ZC - 1);
        int u = col >> 2, g = col & 3;
        const float* Wg = (g == 0) ? Wf : (g == 1) ? Wi : (g == 2) ? Wc : Wo;
        float v = Wg[k * U_ + u];
        __nv_bfloat16 hi = __float2bfloat16(v);
        g_W_hi[idx] = hi;
        g_W_lo[idx] = __float2bfloat16(v - __bfloat162float(hi));
    }
    if (idx < ZC) {
        int u = idx >> 2, g = idx & 3;
        g_bias[idx] = ((g == 0) ? bf : (g == 1) ? bi : (g == 2) ? bc : bo)[u];
    }
    if (idx < B_ * U_) {
        g_Hhi[0][idx] = __float2bfloat16(0.f);
        g_Hlo[0][idx] = __float2bfloat16(0.f);
    }
    if (idx == 0) g_barrier = 0u;
}

// ---------------- phase 1: xw[t][b][col] = x @ Wp + bias, bf16x3 mma ----------------
__global__ __launch_bounds__(128) void xw_gemm_kernel(const float* __restrict__ x)
{
    __shared__ __nv_bfloat16 As_hi[64][24], As_lo[64][24];
    __shared__ __nv_bfloat16 Bs_hi[16][72], Bs_lo[16][72];

    const int tid = threadIdx.x;
    const int warp = tid >> 5, lane = tid & 31;
    const int wm = warp >> 1, wn = warp & 1;
    const int rowbase = blockIdx.y * 64;     // row in M = B*T (row = b*T + t)
    const int colbase = blockIdx.x * 64;

    float acc[2][4][4];
    #pragma unroll
    for (int i = 0; i < 2; i++)
        #pragma unroll
        for (int j = 0; j < 4; j++)
            #pragma unroll
            for (int v = 0; v < 4; v++) acc[i][j][v] = 0.f;

    for (int kk = 0; kk < D_; kk += 16) {
        #pragma unroll
        for (int i = 0; i < 8; i++) {
            int e = tid + i * 128;
            int r = e >> 4, k = e & 15;
            float v = x[(size_t)(rowbase + r) * D_ + kk + k];
            __nv_bfloat16 hi = __float2bfloat16(v);
            As_hi[r][k] = hi;
            As_lo[r][k] = __float2bfloat16(v - __bfloat162float(hi));
        }
        #pragma unroll
        for (int i = 0; i < 8; i++) {
            int e = tid + i * 128;
            int k = e >> 6, n = e & 63;
            size_t gi = (size_t)(kk + k) * ZC + colbase + n;
            Bs_hi[k][n] = g_W_hi[gi];
            Bs_lo[k][n] = g_W_lo[gi];
        }
        __syncthreads();

        uint32_t ah[2][4], al[2][4], bh[4][2], bl[4][2];
        const int arow_in = lane & 15, ahalf = (lane >> 4) * 8;
        #pragma unroll
        for (int mi = 0; mi < 2; mi++) {
            int r = wm * 32 + mi * 16 + arow_in;
            ldsm4(ah[mi][0], ah[mi][1], ah[mi][2], ah[mi][3], smem_u32(&As_hi[r][ahalf]));
            ldsm4(al[mi][0], al[mi][1], al[mi][2], al[mi][3], smem_u32(&As_lo[r][ahalf]));
        }
        const int brow = lane & 15;
        #pragma unroll
        for (int ni = 0; ni < 4; ni++) {
            int bcol = wn * 32 + ni * 8;
            ldsm2t(bh[ni][0], bh[ni][1], smem_u32(&Bs_hi[brow][bcol]));
            ldsm2t(bl[ni][0], bl[ni][1], smem_u32(&Bs_lo[brow][bcol]));
        }
        #pragma unroll
        for (int mi = 0; mi < 2; mi++)
            #pragma unroll
            for (int ni = 0; ni < 4; ni++) {
                mma_bf16(acc[mi][ni], ah[mi], bh[ni]);
                mma_bf16(acc[mi][ni], ah[mi], bl[ni]);
                mma_bf16(acc[mi][ni], al[mi], bh[ni]);
            }
        __syncthreads();
    }

    const int r0 = lane >> 2, c0 = (lane & 3) * 2;
    #pragma unroll
    for (int mi = 0; mi < 2; mi++)
        #pragma unroll
        for (int ni = 0; ni < 4; ni++) {
            int c = colbase + wn * 32 + ni * 8 + c0;
            int R = rowbase + wm * 32 + mi * 16 + r0;
            float bx = g_bias[c], by = g_bias[c + 1];
            {
                int b = R >> 9, t = R & 511;
                float2 v = make_float2(acc[mi][ni][0] + bx, acc[mi][ni][1] + by);
                *(float2*)&g_xw[((size_t)t * B_ + b) * ZC + c] = v;
            }
            {
                int R2 = R + 8;
                int b = R2 >> 9, t = R2 & 511;
                float2 v = make_float2(acc[mi][ni][2] + bx, acc[mi][ni][3] + by);
                *(float2*)&g_xw[((size_t)t * B_ + b) * ZC + c] = v;
            }
        }
}

// ---------------- phase 2: persistent recurrence kernel ----------------
// 128 CTAs (32 col-tiles x 4 row-tiles), 128 threads each, 1 CTA/SM.
// Per CTA: its 512x64 Ur slice lives in smem for all 512 steps (XOR-swizzled),
// c and peephole vectors live in smem, h ping-pongs through global as bf16 hi/lo.

// smem layout sizes (bytes)
#define SM_BHI   0
#define SM_BLO   (512*64*2)                        //  65536
#define SM_AHI   (SM_BLO + 512*64*2)               // 131072
#define SM_ALO   (SM_AHI + 2*64*64*2)              // 147456
#define SM_ZS    (SM_ALO + 2*64*64*2)              // 163840
#define SM_CS    (SM_ZS + 64*68*4)                 // 181248
#define SM_PS    (SM_CS + 1024*4)                  // 185344
#define SM_TOTAL (SM_PS + 48*4)                    // 185536

__device__ __forceinline__ void grid_barrier(unsigned target) {
    __syncthreads();
    if (threadIdx.x == 0) {
        __threadfence();                           // release H writes
        atomicAdd(&g_barrier, 1u);
        unsigned v;
        do {
            asm volatile("ld.acquire.gpu.global.u32 %0, [%1];"
                         : "=r"(v) : "l"(&g_barrier) : "memory");
        } while (v < target);
    }
    __syncthreads();
}

__global__ __launch_bounds__(128, 1) void lstm_persistent(const float* __restrict__ Pf,
                                                          const float* __restrict__ Pi,
                                                          const float* __restrict__ Po,
                                                          float* __restrict__ out)
{
    extern __shared__ char sm[];
    __nv_bfloat16* Bhi = (__nv_bfloat16*)(sm + SM_BHI);   // [512][64] swizzled
    __nv_bfloat16* Blo = (__nv_bfloat16*)(sm + SM_BLO);
    __nv_bfloat16* Ahi = (__nv_bfloat16*)(sm + SM_AHI);   // [2][64][64] swizzled
    __nv_bfloat16* Alo = (__nv_bfloat16*)(sm + SM_ALO);
    float*         zs  = (float*)(sm + SM_ZS);            // [64][68]
    float*         Cs  = (float*)(sm + SM_CS);            // [64*16]
    float*         Ps  = (float*)(sm + SM_PS);            // [3][16]

    const int tid  = threadIdx.x;
    const int warp = tid >> 5, lane = tid & 31;
    const int wm = warp >> 1, wn = warp & 1;
    const int colCTA = blockIdx.x & 31, rowCTA = blockIdx.x >> 5;
    const int colbase = colCTA * 64;
    const int rowbase = rowCTA * 64;

    // ---- one-time: load persistent Ur slice, zero c, load peepholes ----
    for (int idx = tid; idx < 512 * 8; idx += 128) {       // 8 chunks of 8 bf16 per row
        int k = idx >> 3, c8 = idx & 7;
        size_t gi = (size_t)k * ZC + colbase + c8 * 8;
        int dst = k * 64 + ((c8 ^ (k & 7)) << 3);
        *(uint4*)&Bhi[dst] = *(const uint4*)&g_Ur_hi[gi];
        *(uint4*)&Blo[dst] = *(const uint4*)&g_Ur_lo[gi];
    }
    for (int e = tid; e < 1024; e += 128) Cs[e] = 0.f;
    if (tid < 16) {
        int u = colCTA * 16 + tid;
        Ps[tid]      = Pf[u];
        Ps[16 + tid] = Pi[u];
        Ps[32 + tid] = Po[u];
    }
    __syncthreads();

    const int r0 = lane >> 2, c0 = (lane & 3) * 2;

    #pragma unroll 1
    for (int t = 0; t < T_; t++) {
        const __nv_bfloat16* __restrict__ Hh = g_Hhi[t & 1];
        const __nv_bfloat16* __restrict__ Hl = g_Hlo[t & 1];

        // prefetch this step's xw tile into registers (hides under MMA loop)
        float2 xv[2][4][2];
        {
            const float* __restrict__ xw_t = g_xw + (size_t)t * (B_ * ZC);
            #pragma unroll
            for (int mi = 0; mi < 2; mi++)
                #pragma unroll
                for (int ni = 0; ni < 4; ni++) {
                    int cg = colbase + wn * 32 + ni * 8 + c0;
                    int bg = rowbase + wm * 32 + mi * 16 + r0;
                    xv[mi][ni][0] = *(const float2*)&xw_t[(size_t)bg * ZC + cg];
                    xv[mi][ni][1] = *(const float2*)&xw_t[(size_t)(bg + 8) * ZC + cg];
                }
        }

        // prologue: stage A chunk 0 (k = 0..63)
        #pragma unroll
        for (int i = 0; i < 4; i++) {
            int seg = tid + i * 128;
            int r = seg >> 3, c8 = seg & 7;
            size_t gi = (size_t)(rowbase + r) * U_ + c8 * 8;
            int dst = r * 64 + ((c8 ^ (r & 7)) << 3);
            *(uint4*)&Ahi[dst] = *(const uint4*)&Hh[gi];
            *(uint4*)&Alo[dst] = *(const uint4*)&Hl[gi];
        }
        __syncthreads();

        float acc[2][4][4];
        #pragma unroll
        for (int i = 0; i < 2; i++)
            #pragma unroll
            for (int j = 0; j < 4; j++)
                #pragma unroll
                for (int v = 0; v < 4; v++) acc[i][j][v] = 0.f;

        #pragma unroll
        for (int kc = 0; kc < 8; kc++) {
            const int cur = kc & 1;
            // issue LDGs for next chunk before MMA work
            uint4 ph[4], pl[4];
            if (kc < 7) {
                #pragma unroll
                for (int i = 0; i < 4; i++) {
                    int seg = tid + i * 128;
                    int r = seg >> 3, c8 = seg & 7;
                    size_t gi = (size_t)(rowbase + r) * U_ + (kc + 1) * 64 + c8 * 8;
                    ph[i] = *(const uint4*)&Hh[gi];
                    pl[i] = *(const uint4*)&Hl[gi];
                }
            }
            // 4 x k16 MMA sub-iters over chunk kc
            #pragma unroll
            for (int kt2 = 0; kt2 < 4; kt2++) {
                uint32_t ah[2][4], al[2][4], bh[4][2], bl[4][2];
                const int khalf = kt2 * 2 + (lane >> 4);      // 8-elem chunk within 64
                #pragma unroll
                for (int mi = 0; mi < 2; mi++) {
                    int r = wm * 32 + mi * 16 + (lane & 15);
                    int off = cur * 4096 + r * 64 + ((khalf ^ (r & 7)) << 3);
                    ldsm4(ah[mi][0], ah[mi][1], ah[mi][2], ah[mi][3], smem_u32(&Ahi[off]));
                    ldsm4(al[mi][0], al[mi][1], al[mi][2], al[mi][3], smem_u32(&Alo[off]));
                }
                const int krow = kc * 64 + kt2 * 16 + (lane & 15);
                #pragma unroll
                for (int ni = 0; ni < 4; ni++) {
                    int bc8 = (wn * 4 + ni) ^ (krow & 7);
                    int off = krow * 64 + (bc8 << 3);
                    ldsm2t(bh[ni][0], bh[ni][1], smem_u32(&Bhi[off]));
                    ldsm2t(bl[ni][0], bl[ni][1], smem_u32(&Blo[off]));
                }
                // 3 passes -> 8-MMA RAW distance per accumulator
                #pragma unroll
                for (int mi = 0; mi < 2; mi++)
                    #pragma unroll
                    for (int ni = 0; ni < 4; ni++)
                        mma_bf16(acc[mi][ni], ah[mi], bh[ni]);
                #pragma unroll
                for (int mi = 0; mi < 2; mi++)
                    #pragma unroll
                    for (int ni = 0; ni < 4; ni++)
                        mma_bf16(acc[mi][ni], ah[mi], bl[ni]);
                #pragma unroll
                for (int mi = 0; mi < 2; mi++)
                    #pragma unroll
                    for (int ni = 0; ni < 4; ni++)
                        mma_bf16(acc[mi][ni], al[mi], bh[ni]);
            }
            // store prefetched chunk into other buffer
            if (kc < 7) {
                #pragma unroll
                for (int i = 0; i < 4; i++) {
                    int seg = tid + i * 128;
                    int r = seg >> 3, c8 = seg & 7;
                    int dst = (cur ^ 1) * 4096 + r * 64 + ((c8 ^ (r & 7)) << 3);
                    *(uint4*)&Ahi[dst] = ph[i];
                    *(uint4*)&Alo[dst] = pl[i];
                }
            }
            __syncthreads();
        }

        // stage z = acc + xw into smem
        #pragma unroll
        for (int mi = 0; mi < 2; mi++)
            #pragma unroll
            for (int ni = 0; ni < 4; ni++) {
                int r = wm * 32 + mi * 16 + r0;
                int cl = wn * 32 + ni * 8 + c0;
                zs[r * 68 + cl]           = acc[mi][ni][0] + xv[mi][ni][0].x;
                zs[r * 68 + cl + 1]       = acc[mi][ni][1] + xv[mi][ni][0].y;
                zs[(r + 8) * 68 + cl]     = acc[mi][ni][2] + xv[mi][ni][1].x;
                zs[(r + 8) * 68 + cl + 1] = acc[mi][ni][3] + xv[mi][ni][1].y;
            }
        __syncthreads();

        // fused peephole-LSTM gate epilogue: c stays in smem, h -> global bf16 hi/lo
        __nv_bfloat16* __restrict__ Hh_n = g_Hhi[(t + 1) & 1];
        __nv_bfloat16* __restrict__ Hl_n = g_Hlo[(t + 1) & 1];
        #pragma unroll
        for (int e = tid; e < 1024; e += 128) {
            int r = e >> 4, ul = e & 15;
            int b = rowbase + r;
            int u = colCTA * 16 + ul;
            float zf = zs[r * 68 + 4 * ul + 0];
            float zi = zs[r * 68 + 4 * ul + 1];
            float zc = zs[r * 68 + 4 * ul + 2];
            float zo = zs[r * 68 + 4 * ul + 3];
            float cold = Cs[e];
            float f  = sigm(zf + cold * Ps[ul]);
            float ig = sigm(zi + cold * Ps[16 + ul]);
            float cc = tanh_(zc);
            float cn = f * cold + ig * cc;
            float o  = sigm(zo + cn * Ps[32 + ul]);
            float hn = o * tanh_(cn);
            Cs[e] = cn;
            __nv_bfloat16 hi = __float2bfloat16(hn);
            int gi = b * U_ + u;
            Hh_n[gi] = hi;
            Hl_n[gi] = __float2bfloat16(hn - __bfloat162float(hi));
            out[((size_t)b * T_ + t) * U_ + u] = hn;
        }

        // grid-wide release/acquire barrier before next step reads Hnext
        if (t < T_ - 1) grid_barrier((unsigned)(t + 1) * 128u);
    }
}

// ---------------- launch ----------------
extern "C" void kernel_launch(void* const* d_in, const int* in_sizes, int n_in,
                              void* d_out, int out_size)
{
    (void)in_sizes; (void)n_in; (void)out_size;
    const float* x  = (const float*)d_in[0];
    const float* Wf = (const float*)d_in[1];
    const float* Uf = (const float*)d_in[2];
    const float* Pf = (const float*)d_in[3];
    const float* bf = (const float*)d_in[4];
    const float* Wi = (const float*)d_in[5];
    const float* Ui = (const float*)d_in[6];
    const float* Pi = (const float*)d_in[7];
    const float* bi = (const float*)d_in[8];
    const float* Wc = (const float*)d_in[9];
    const float* Uc = (const float*)d_in[10];
    const float* bc = (const float*)d_in[11];
    const float* Wo = (const float*)d_in[12];
    const float* Uo = (const float*)d_in[13];
    const float* Po = (const float*)d_in[14];
    const float* bo = (const float*)d_in[15];
    float* out = (float*)d_out;

    static bool attr_done = false;
    if (!attr_done) {
        cudaFuncSetAttribute(lstm_persistent,
                             cudaFuncAttributeMaxDynamicSharedMemorySize, SM_TOTAL);
        attr_done = true;
    }

    // 1) pack/split weights, zero state + barrier (every call: deterministic graph)
    prep_kernel<<<4096, 256>>>(Uf, Ui, Uc, Uo, Wf, Wi, Wc, Wo, bf, bi, bc, bo);

    // 2) all input projections in one big GEMM: M=131072, N=2048, K=256
    xw_gemm_kernel<<<dim3(32, 2048), 128>>>(x);

    // 3) persistent recurrence: 128 CTAs, 512 steps, grid barriers between steps
    lstm_persistent<<<128, 128, SM_TOTAL>>>(Pf, Pi, Po, out);
}